// round 9
// baseline (speedup 1.0000x reference)
#include <cuda_runtime.h>
#include <math.h>

#define B_   32
#define T_   512
#define H_   1024
#define G3   3072
#define NCTA 128
#define NTHR 512
#define KSL  32          // k per slice (32 slices)

typedef unsigned long long u64;

// ---------------- device scratch ----------------
__device__ float        g_GX[(size_t)B_ * T_ * G3];
__device__ float        g_h2[2][H_][B_];              // hidden, transposed [k][b]
__device__ float        g_RP[(size_t)NCTA * H_ * 4 * 6];  // repacked R, 12 MB
__device__ unsigned int g_counters[T_ + 2];

// ---------------- f32x2 helpers ----------------
__device__ __forceinline__ void fma2(u64 &d, u64 a, u64 b) {
    asm("fma.rn.f32x2 %0, %1, %2, %0;" : "+l"(d) : "l"(a), "l"(b));
}
__device__ __forceinline__ u64 splat2(float v) {
    u64 r; asm("mov.b64 %0, {%1, %1};" : "=l"(r) : "f"(v)); return r;
}
__device__ __forceinline__ float2 unpk(u64 v) {
    float2 r; asm("mov.b64 {%0, %1}, %2;" : "=f"(r.x), "=f"(r.y) : "l"(v)); return r;
}

// ---------------- init ----------------
__global__ void init_kernel(const float* __restrict__ hidden) {
    int tid = blockIdx.x * blockDim.x + threadIdx.x;
    if (tid < T_ + 2) g_counters[tid] = 0u;
    for (int i = tid; i < B_ * H_; i += gridDim.x * blockDim.x) {
        int b = i / H_, j = i % H_;
        g_h2[0][j][b] = hidden[i];
    }
}

// ---------------- repack R: RT [k][g*1024+j] -> g_RP per-CTA records ----------------
// record (c, k, up) = {z0, r0, n0, z1, r1, n1} for units j = c*8 + up*2 + {0,1}
__global__ void repack_kernel(const float* __restrict__ RT) {
    int idx = blockIdx.x * blockDim.x + threadIdx.x;   // 0 .. 128*1024*4-1
    if (idx >= NCTA * H_ * 4) return;
    int up = idx & 3;
    int k  = (idx >> 2) & (H_ - 1);
    int c  = idx >> 12;
    int j  = c * 8 + up * 2;
    const float* rk = RT + (size_t)k * G3;
    float z0 = rk[j],        r0 = rk[1024 + j],     n0 = rk[2048 + j];
    float z1 = rk[j + 1],    r1 = rk[1024 + j + 1], n1 = rk[2048 + j + 1];
    float* dst = g_RP + ((size_t)(c * H_ + k) * 4 + up) * 6;
    *(float2*)(dst)     = make_float2(z0, r0);
    *(float2*)(dst + 2) = make_float2(n0, z1);
    *(float2*)(dst + 4) = make_float2(r1, n1);
}

// ---------------- GX GEMM (R4-proven BN=64 f32x2 version) ----------------
#define BM 128
#define BN 64
#define BK 16

__global__ void __launch_bounds__(256)
gx_kernel(const int* __restrict__ x, const float* __restrict__ emb,
          const float* __restrict__ W, const float* __restrict__ bias) {
    __shared__ float As[BK][BM + 4];
    __shared__ float Bs[BK][BN + 4];
    __shared__ int   toks[BM];

    const int m0  = blockIdx.x * BM;
    const int n0  = blockIdx.y * BN;
    const int tid = threadIdx.x;
    const int ty  = tid >> 4;
    const int tx  = tid & 15;

    if (tid < BM) toks[tid] = x[m0 + tid];
    __syncthreads();

    u64 acc[4][4];
#pragma unroll
    for (int p = 0; p < 4; p++)
#pragma unroll
        for (int c = 0; c < 4; c++) acc[p][c] = 0ull;

    for (int k0 = 0; k0 < H_; k0 += BK) {
#pragma unroll
        for (int r = 0; r < 2; r++) {
            int s   = tid + r * 256;
            int row = s >> 2;
            int kq  = s & 3;
            float4 v = *(const float4*)(emb + (size_t)toks[row] * H_ + k0 + kq * 4);
            As[kq * 4 + 0][row] = v.x;
            As[kq * 4 + 1][row] = v.y;
            As[kq * 4 + 2][row] = v.z;
            As[kq * 4 + 3][row] = v.w;
        }
        {
            int kk = tid >> 4, c4 = tid & 15;
            float4 v = *(const float4*)(W + (size_t)(k0 + kk) * G3 + n0 + c4 * 4);
            *(float4*)&Bs[kk][c4 * 4] = v;
        }
        __syncthreads();

#pragma unroll
        for (int kk = 0; kk < BK; kk++) {
            ulonglong2 av0 = *(const ulonglong2*)&As[kk][ty * 8];
            ulonglong2 av1 = *(const ulonglong2*)&As[kk][ty * 8 + 4];
            float4 bq = *(const float4*)&Bs[kk][tx * 4];
            u64 b0 = splat2(bq.x), b1 = splat2(bq.y), b2 = splat2(bq.z), b3 = splat2(bq.w);
            fma2(acc[0][0], av0.x, b0); fma2(acc[0][1], av0.x, b1);
            fma2(acc[0][2], av0.x, b2); fma2(acc[0][3], av0.x, b3);
            fma2(acc[1][0], av0.y, b0); fma2(acc[1][1], av0.y, b1);
            fma2(acc[1][2], av0.y, b2); fma2(acc[1][3], av0.y, b3);
            fma2(acc[2][0], av1.x, b0); fma2(acc[2][1], av1.x, b1);
            fma2(acc[2][2], av1.x, b2); fma2(acc[2][3], av1.x, b3);
            fma2(acc[3][0], av1.y, b0); fma2(acc[3][1], av1.y, b1);
            fma2(acc[3][2], av1.y, b2); fma2(acc[3][3], av1.y, b3);
        }
        __syncthreads();
    }

    float4 biv = *(const float4*)(bias + n0 + tx * 4);
#pragma unroll
    for (int p = 0; p < 4; p++) {
        float2 c0 = unpk(acc[p][0]), c1 = unpk(acc[p][1]);
        float2 c2 = unpk(acc[p][2]), c3 = unpk(acc[p][3]);
        int m = m0 + ty * 8 + p * 2;
        float4 oe = {c0.x + biv.x, c1.x + biv.y, c2.x + biv.z, c3.x + biv.w};
        float4 oo = {c0.y + biv.x, c1.y + biv.y, c2.y + biv.z, c3.y + biv.w};
        *(float4*)(g_GX + (size_t)m * G3 + n0 + tx * 4)       = oe;
        *(float4*)(g_GX + (size_t)(m + 1) * G3 + n0 + tx * 4) = oo;
    }
}

// ---------------- persistent recurrence: R via L1-cached LDG, smem = red only ----------------
// Mapping A: up = tid&3, bo = (tid>>2)&3, ks = tid>>4.
// R: 3 x LDG.64 per k from g_RP (4 bo-lanes share each address -> coalescer dedup;
//    96 KB per-CTA slice stays L1-resident because smem is now only ~97 KB).
// red layout: red[(ks*4+up)*194 + (g*2+uo)*32 + batch]
__global__ void __launch_bounds__(NTHR, 1)
gru_persist(const int* __restrict__ x, const float* __restrict__ bias,
            float* __restrict__ out, int out_size) {
    extern __shared__ float red[];   // 24832 floats (97 KB)

    const int c   = blockIdx.x;
    const int j0  = c * 8;
    const int tid = threadIdx.x;
    // mapping A
    const int up = tid & 3;
    const int bo = (tid >> 2) & 3;
    const int ks = tid >> 4;            // 0..31
    // mapping B (gates)
    const bool gates = (tid < 256);
    const int u2  = tid & 7;
    const int b2  = tid >> 3;
    const int j2  = j0 + u2;
    const int up2 = u2 >> 1;
    const int uo2 = u2 & 1;

    float brz = 0.0f, brr = 0.0f, brn = 0.0f;
    if (gates) {
        brz = bias[G3 + j2];
        brr = bias[G3 + 1024 + j2];
        brn = bias[G3 + 2048 + j2];
    }

    const float* gx_row = gates ? (g_GX + (size_t)b2 * T_ * G3) : g_GX;
    const int*   xrow   = gates ? (x + b2 * T_) : x;
    const int    k0     = ks * KSL;
    u64*         redu   = (u64*)red;
    const int    rbase  = (ks * 4 + up) * 97;
    const float* rp0    = g_RP + ((size_t)(c * H_ + k0) * 4 + up) * 6;
    const bool   write_state = (out_size >= B_ * T_ * H_ + B_ * H_);

    for (int t = 0; t < T_; t++) {
        const float* hcur = &g_h2[t & 1][0][0];

        // prefetch gate-phase inputs
        float xz = 0.f, xr = 0.f, xn = 0.f, hp = 0.f;
        int tok = 1;
        if (gates) {
            xz  = __ldcs(gx_row + (size_t)t * G3 + j2);
            xr  = __ldcs(gx_row + (size_t)t * G3 + 1024 + j2);
            xn  = __ldcs(gx_row + (size_t)t * G3 + 2048 + j2);
            hp  = __ldcg(hcur + j2 * B_ + b2);
            tok = __ldg(xrow + t);
        }

        // ---- matvec partial: 2 units x 3 gates x 8 batches over 32-k slice ----
        u64 A[2][3][4];
#pragma unroll
        for (int uo = 0; uo < 2; uo++)
#pragma unroll
            for (int g = 0; g < 3; g++)
#pragma unroll
                for (int q = 0; q < 4; q++) A[uo][g][q] = 0ull;

        const float* hk = hcur + (size_t)k0 * B_ + bo * 8;
        const float* rk = rp0;
#pragma unroll 4
        for (int k = 0; k < KSL; k++) {
            ulonglong2 ha = __ldcg((const ulonglong2*)hk);        // batches 0-3 of octet
            ulonglong2 hb = __ldcg((const ulonglong2*)(hk + 4));  // batches 4-7
            float2 rA = *(const float2*)(rk);      // z0 r0   (L1-cached LDG)
            float2 rB = *(const float2*)(rk + 2);  // n0 z1
            float2 rC = *(const float2*)(rk + 4);  // r1 n1
            u64 rz0 = splat2(rA.x), rr0 = splat2(rA.y), rn0 = splat2(rB.x);
            u64 rz1 = splat2(rB.y), rr1 = splat2(rC.x), rn1 = splat2(rC.y);
            fma2(A[0][0][0], ha.x, rz0); fma2(A[0][0][1], ha.y, rz0);
            fma2(A[0][0][2], hb.x, rz0); fma2(A[0][0][3], hb.y, rz0);
            fma2(A[0][1][0], ha.x, rr0); fma2(A[0][1][1], ha.y, rr0);
            fma2(A[0][1][2], hb.x, rr0); fma2(A[0][1][3], hb.y, rr0);
            fma2(A[0][2][0], ha.x, rn0); fma2(A[0][2][1], ha.y, rn0);
            fma2(A[0][2][2], hb.x, rn0); fma2(A[0][2][3], hb.y, rn0);
            fma2(A[1][0][0], ha.x, rz1); fma2(A[1][0][1], ha.y, rz1);
            fma2(A[1][0][2], hb.x, rz1); fma2(A[1][0][3], hb.y, rz1);
            fma2(A[1][1][0], ha.x, rr1); fma2(A[1][1][1], ha.y, rr1);
            fma2(A[1][1][2], hb.x, rr1); fma2(A[1][1][3], hb.y, rr1);
            fma2(A[1][2][0], ha.x, rn1); fma2(A[1][2][1], ha.y, rn1);
            fma2(A[1][2][2], hb.x, rn1); fma2(A[1][2][3], hb.y, rn1);
            hk += B_; rk += 24;
        }
#pragma unroll
        for (int uo = 0; uo < 2; uo++)
#pragma unroll
            for (int g = 0; g < 3; g++) {
                int base = rbase + ((g * 2 + uo) * 32 + bo * 8) / 2;
                redu[base + 0] = A[uo][g][0];
                redu[base + 1] = A[uo][g][1];
                redu[base + 2] = A[uo][g][2];
                redu[base + 3] = A[uo][g][3];
            }
        __syncthreads();

        // ---- reduce + gates (threads 0..255) ----
        if (gates) {
            float az = 0.0f, ar = 0.0f, an = 0.0f;
#pragma unroll
            for (int kss = 0; kss < 32; kss++) {
                int o = (kss * 4 + up2) * 194 + uo2 * 32 + b2;
                az += red[o];
                ar += red[o + 64];
                an += red[o + 128];
            }
            float zz = 1.0f / (1.0f + expf(-(xz + az + brz)));
            float rg = 1.0f / (1.0f + expf(-(xr + ar + brr)));
            float hh = tanhf(xn + rg * (an + brn));
            float hnew = zz * hp + (1.0f - zz) * hh;
            if (tok == 0) hnew = hp;

            out[((size_t)b2 * T_ + t) * H_ + j2] = hnew;
            g_h2[(t + 1) & 1][j2][b2] = hnew;
            if (t == T_ - 1 && write_state)
                out[(size_t)B_ * T_ * H_ + (size_t)b2 * H_ + j2] = hnew;
        }

        // ---- grid barrier ----
        if (t < T_ - 1) {
            __syncthreads();
            if (tid == 0) {
                unsigned int* ctr = &g_counters[t + 1];
                asm volatile("red.release.gpu.global.add.u32 [%0], %1;"
                             :: "l"(ctr), "r"(1u) : "memory");
                unsigned int v;
                do {
                    asm volatile("ld.acquire.gpu.global.u32 %0, [%1];"
                                 : "=r"(v) : "l"(ctr) : "memory");
                } while (v < (unsigned)NCTA);
            }
            __syncthreads();
        }
    }
}

// ---------------- launch ----------------
extern "C" void kernel_launch(void* const* d_in, const int* in_sizes, int n_in,
                              void* d_out, int out_size) {
    const int*   x      = (const int*)d_in[0];
    const float* hidden = (const float*)d_in[1];
    const float* emb    = (const float*)d_in[2];
    const float* W      = (const float*)d_in[3];
    const float* RT     = (const float*)d_in[4];
    const float* bias   = (const float*)d_in[5];
    float*       out    = (float*)d_out;

    const int smem = 24832 * 4;   // 99328 B (red only)
    cudaFuncSetAttribute(gru_persist, cudaFuncAttributeMaxDynamicSharedMemorySize, smem);

    // 4 launches/call: ncu's sample (4th user launch) lands on gru_persist
    init_kernel<<<64, 256>>>(hidden);

    dim3 grid_gx(16384 / BM, G3 / BN);   // 128 x 48
    gx_kernel<<<grid_gx, 256>>>(x, emb, W, bias);

    repack_kernel<<<(NCTA * H_ * 4) / 256, 256>>>(RT);

    gru_persist<<<NCTA, NTHR, smem>>>(x, bias, out, out_size);
}

// round 10
// speedup vs baseline: 1.1651x; 1.1651x over previous
#include <cuda_runtime.h>
#include <math.h>

#define B_   32
#define T_   512
#define H_   1024
#define G3   3072
#define NCTA 128
#define NTHR 512
#define KSL  32          // k per slice (32 slices)

typedef unsigned long long u64;

// ---------------- device scratch ----------------
__device__ float        g_GX[(size_t)B_ * T_ * G3];
__device__ float        g_h2[2][H_][B_];              // hidden, transposed [k][b]
__device__ unsigned int g_counters[T_ + 2];

// ---------------- f32x2 helpers ----------------
__device__ __forceinline__ void fma2(u64 &d, u64 a, u64 b) {
    asm("fma.rn.f32x2 %0, %1, %2, %0;" : "+l"(d) : "l"(a), "l"(b));
}
__device__ __forceinline__ u64 splat2(float v) {
    u64 r; asm("mov.b64 %0, {%1, %1};" : "=l"(r) : "f"(v)); return r;
}
__device__ __forceinline__ float2 unpk(u64 v) {
    float2 r; asm("mov.b64 {%0, %1}, %2;" : "=f"(r.x), "=f"(r.y) : "l"(v)); return r;
}

// ---------------- init ----------------
__global__ void init_kernel(const float* __restrict__ hidden) {
    int tid = blockIdx.x * blockDim.x + threadIdx.x;
    if (tid < T_ + 2) g_counters[tid] = 0u;
    for (int i = tid; i < B_ * H_; i += gridDim.x * blockDim.x) {
        int b = i / H_, j = i % H_;
        g_h2[0][j][b] = hidden[i];
    }
}

__global__ void spacer_kernel() {}

// ---------------- GX GEMM: BN=64 f32x2 + register double-buffered tile loads ----------------
#define BM 128
#define BN 64
#define BK 16

__global__ void __launch_bounds__(256)
gx_kernel(const int* __restrict__ x, const float* __restrict__ emb,
          const float* __restrict__ W, const float* __restrict__ bias) {
    __shared__ float As[BK][BM + 4];
    __shared__ float Bs[BK][BN + 4];
    __shared__ int   toks[BM];

    const int m0  = blockIdx.x * BM;
    const int n0  = blockIdx.y * BN;
    const int tid = threadIdx.x;
    const int ty  = tid >> 4;
    const int tx  = tid & 15;

    if (tid < BM) toks[tid] = x[m0 + tid];
    __syncthreads();

    // A-load thread mapping (two rounds), B-load mapping
    const int arow0 = tid >> 2,          akq0 = tid & 3;
    const int arow1 = (tid + 256) >> 2,  akq1 = (tid + 256) & 3;
    const int bkk   = tid >> 4,          bc4  = tid & 15;
    const size_t aoff0 = (size_t)toks[arow0] * H_ + akq0 * 4;
    const size_t aoff1 = (size_t)toks[arow1] * H_ + akq1 * 4;

    u64 acc[4][4];
#pragma unroll
    for (int p = 0; p < 4; p++)
#pragma unroll
        for (int c = 0; c < 4; c++) acc[p][c] = 0ull;

    // preload tile 0 into registers
    float4 pa0 = *(const float4*)(emb + aoff0);
    float4 pa1 = *(const float4*)(emb + aoff1);
    float4 pb  = *(const float4*)(W + (size_t)bkk * G3 + n0 + bc4 * 4);

    for (int k0 = 0; k0 < H_; k0 += BK) {
        // store prefetched tile to smem (A transposed)
        As[akq0 * 4 + 0][arow0] = pa0.x;
        As[akq0 * 4 + 1][arow0] = pa0.y;
        As[akq0 * 4 + 2][arow0] = pa0.z;
        As[akq0 * 4 + 3][arow0] = pa0.w;
        As[akq1 * 4 + 0][arow1] = pa1.x;
        As[akq1 * 4 + 1][arow1] = pa1.y;
        As[akq1 * 4 + 2][arow1] = pa1.z;
        As[akq1 * 4 + 3][arow1] = pa1.w;
        *(float4*)&Bs[bkk][bc4 * 4] = pb;
        __syncthreads();

        // issue next tile's gmem loads (latency hidden under compute)
        if (k0 + BK < H_) {
            int kn = k0 + BK;
            pa0 = *(const float4*)(emb + aoff0 + kn);
            pa1 = *(const float4*)(emb + aoff1 + kn);
            pb  = *(const float4*)(W + (size_t)(kn + bkk) * G3 + n0 + bc4 * 4);
        }

#pragma unroll
        for (int kk = 0; kk < BK; kk++) {
            ulonglong2 av0 = *(const ulonglong2*)&As[kk][ty * 8];
            ulonglong2 av1 = *(const ulonglong2*)&As[kk][ty * 8 + 4];
            float4 bq = *(const float4*)&Bs[kk][tx * 4];
            u64 b0 = splat2(bq.x), b1 = splat2(bq.y), b2 = splat2(bq.z), b3 = splat2(bq.w);
            fma2(acc[0][0], av0.x, b0); fma2(acc[0][1], av0.x, b1);
            fma2(acc[0][2], av0.x, b2); fma2(acc[0][3], av0.x, b3);
            fma2(acc[1][0], av0.y, b0); fma2(acc[1][1], av0.y, b1);
            fma2(acc[1][2], av0.y, b2); fma2(acc[1][3], av0.y, b3);
            fma2(acc[2][0], av1.x, b0); fma2(acc[2][1], av1.x, b1);
            fma2(acc[2][2], av1.x, b2); fma2(acc[2][3], av1.x, b3);
            fma2(acc[3][0], av1.y, b0); fma2(acc[3][1], av1.y, b1);
            fma2(acc[3][2], av1.y, b2); fma2(acc[3][3], av1.y, b3);
        }
        __syncthreads();
    }

    float4 biv = *(const float4*)(bias + n0 + tx * 4);
#pragma unroll
    for (int p = 0; p < 4; p++) {
        float2 c0 = unpk(acc[p][0]), c1 = unpk(acc[p][1]);
        float2 c2 = unpk(acc[p][2]), c3 = unpk(acc[p][3]);
        int m = m0 + ty * 8 + p * 2;
        float4 oe = {c0.x + biv.x, c1.x + biv.y, c2.x + biv.z, c3.x + biv.w};
        float4 oo = {c0.y + biv.x, c1.y + biv.y, c2.y + biv.z, c3.y + biv.w};
        *(float4*)(g_GX + (size_t)m * G3 + n0 + tx * 4)       = oe;
        *(float4*)(g_GX + (size_t)(m + 1) * G3 + n0 + tx * 4) = oo;
    }
}

// ---------------- persistent recurrence (exact R8 best config) ----------------
// Mapping A: up = tid&3 (unit pair), bo = (tid>>2)&3 (batch octet), ks = tid>>4 (0..31).
// Rs layout: Rs[k*24 + up*6 + {z0,r0,n0,z1,r1,n1}]  (96 KB)
// red layout: red[(ks*4+up)*194 + (g*2+uo)*32 + batch]  (97 KB)
__global__ void __launch_bounds__(NTHR, 1)
gru_persist(const int* __restrict__ x, const float* __restrict__ RT,
            const float* __restrict__ bias, float* __restrict__ out, int out_size) {
    extern __shared__ float sm[];
    float* Rs  = sm;             // 24576 floats
    float* red = sm + 24576;     // 24832 floats

    const int c   = blockIdx.x;
    const int j0  = c * 8;
    const int tid = threadIdx.x;
    // mapping A
    const int up = tid & 3;
    const int bo = (tid >> 2) & 3;
    const int ks = tid >> 4;            // 0..31
    // mapping B (gates)
    const bool gates = (tid < 256);
    const int u2  = tid & 7;
    const int b2  = tid >> 3;
    const int j2  = j0 + u2;
    const int up2 = u2 >> 1;
    const int uo2 = u2 & 1;

    // stage R once: Rs[k*24 + up*6 + uo*3 + g]
    for (int s = tid; s < 1024 * 24; s += NTHR) {
        int k = s / 24, r = s % 24;
        int upp = r / 6, e = r % 6;
        int uo = e / 3, g = e % 3;
        Rs[k * 24 + upp * 6 + e] = RT[(size_t)k * G3 + g * 1024 + j0 + upp * 2 + uo];
    }
    float brz = 0.0f, brr = 0.0f, brn = 0.0f;
    if (gates) {
        brz = bias[G3 + j2];
        brr = bias[G3 + 1024 + j2];
        brn = bias[G3 + 2048 + j2];
    }
    __syncthreads();

    const float* gx_row = gates ? (g_GX + (size_t)b2 * T_ * G3) : g_GX;
    const int*   xrow   = gates ? (x + b2 * T_) : x;
    const int    k0     = ks * KSL;
    u64*         redu   = (u64*)red;
    const int    rbase  = (ks * 4 + up) * 97;
    const bool   write_state = (out_size >= B_ * T_ * H_ + B_ * H_);

    for (int t = 0; t < T_; t++) {
        const float* hcur = &g_h2[t & 1][0][0];

        float xz = 0.f, xr = 0.f, xn = 0.f, hp = 0.f;
        int tok = 1;
        if (gates) {
            xz  = __ldcs(gx_row + (size_t)t * G3 + j2);
            xr  = __ldcs(gx_row + (size_t)t * G3 + 1024 + j2);
            xn  = __ldcs(gx_row + (size_t)t * G3 + 2048 + j2);
            hp  = __ldcg(hcur + j2 * B_ + b2);
            tok = __ldg(xrow + t);
        }

        u64 A[2][3][4];
#pragma unroll
        for (int uo = 0; uo < 2; uo++)
#pragma unroll
            for (int g = 0; g < 3; g++)
#pragma unroll
                for (int q = 0; q < 4; q++) A[uo][g][q] = 0ull;

        const float* hk = hcur + (size_t)k0 * B_ + bo * 8;
        const float* rk = Rs + k0 * 24 + up * 6;
#pragma unroll 4
        for (int k = 0; k < KSL; k++) {
            ulonglong2 ha = __ldcg((const ulonglong2*)hk);
            ulonglong2 hb = __ldcg((const ulonglong2*)(hk + 4));
            float2 rA = *(const float2*)(rk);
            float2 rB = *(const float2*)(rk + 2);
            float2 rC = *(const float2*)(rk + 4);
            u64 rz0 = splat2(rA.x), rr0 = splat2(rA.y), rn0 = splat2(rB.x);
            u64 rz1 = splat2(rB.y), rr1 = splat2(rC.x), rn1 = splat2(rC.y);
            fma2(A[0][0][0], ha.x, rz0); fma2(A[0][0][1], ha.y, rz0);
            fma2(A[0][0][2], hb.x, rz0); fma2(A[0][0][3], hb.y, rz0);
            fma2(A[0][1][0], ha.x, rr0); fma2(A[0][1][1], ha.y, rr0);
            fma2(A[0][1][2], hb.x, rr0); fma2(A[0][1][3], hb.y, rr0);
            fma2(A[0][2][0], ha.x, rn0); fma2(A[0][2][1], ha.y, rn0);
            fma2(A[0][2][2], hb.x, rn0); fma2(A[0][2][3], hb.y, rn0);
            fma2(A[1][0][0], ha.x, rz1); fma2(A[1][0][1], ha.y, rz1);
            fma2(A[1][0][2], hb.x, rz1); fma2(A[1][0][3], hb.y, rz1);
            fma2(A[1][1][0], ha.x, rr1); fma2(A[1][1][1], ha.y, rr1);
            fma2(A[1][1][2], hb.x, rr1); fma2(A[1][1][3], hb.y, rr1);
            fma2(A[1][2][0], ha.x, rn1); fma2(A[1][2][1], ha.y, rn1);
            fma2(A[1][2][2], hb.x, rn1); fma2(A[1][2][3], hb.y, rn1);
            hk += B_; rk += 24;
        }
#pragma unroll
        for (int uo = 0; uo < 2; uo++)
#pragma unroll
            for (int g = 0; g < 3; g++) {
                int base = rbase + ((g * 2 + uo) * 32 + bo * 8) / 2;
                redu[base + 0] = A[uo][g][0];
                redu[base + 1] = A[uo][g][1];
                redu[base + 2] = A[uo][g][2];
                redu[base + 3] = A[uo][g][3];
            }
        __syncthreads();

        if (gates) {
            float az = 0.0f, ar = 0.0f, an = 0.0f;
#pragma unroll
            for (int kss = 0; kss < 32; kss++) {
                int o = (kss * 4 + up2) * 194 + uo2 * 32 + b2;
                az += red[o];
                ar += red[o + 64];
                an += red[o + 128];
            }
            float zz = 1.0f / (1.0f + expf(-(xz + az + brz)));
            float rg = 1.0f / (1.0f + expf(-(xr + ar + brr)));
            float hh = tanhf(xn + rg * (an + brn));
            float hnew = zz * hp + (1.0f - zz) * hh;
            if (tok == 0) hnew = hp;

            out[((size_t)b2 * T_ + t) * H_ + j2] = hnew;
            g_h2[(t + 1) & 1][j2][b2] = hnew;
            if (t == T_ - 1 && write_state)
                out[(size_t)B_ * T_ * H_ + (size_t)b2 * H_ + j2] = hnew;
        }

        if (t < T_ - 1) {
            __syncthreads();
            if (tid == 0) {
                unsigned int* ctr = &g_counters[t + 1];
                asm volatile("red.release.gpu.global.add.u32 [%0], %1;"
                             :: "l"(ctr), "r"(1u) : "memory");
                unsigned int v;
                do {
                    asm volatile("ld.acquire.gpu.global.u32 %0, [%1];"
                                 : "=r"(v) : "l"(ctr) : "memory");
                } while (v < (unsigned)NCTA);
            }
            __syncthreads();
        }
    }
}

// ---------------- launch ----------------
extern "C" void kernel_launch(void* const* d_in, const int* in_sizes, int n_in,
                              void* d_out, int out_size) {
    const int*   x      = (const int*)d_in[0];
    const float* hidden = (const float*)d_in[1];
    const float* emb    = (const float*)d_in[2];
    const float* W      = (const float*)d_in[3];
    const float* RT     = (const float*)d_in[4];
    const float* bias   = (const float*)d_in[5];
    float*       out    = (float*)d_out;

    const int smem = (24576 + 24832) * 4;   // 197632 B
    cudaFuncSetAttribute(gru_persist, cudaFuncAttributeMaxDynamicSharedMemorySize, smem);

    // 4 launches/call: ncu's sample (4th user launch) lands on gru_persist
    init_kernel<<<64, 256>>>(hidden);

    dim3 grid_gx(16384 / BM, G3 / BN);   // 128 x 48
    gx_kernel<<<grid_gx, 256>>>(x, emb, W, bias);

    spacer_kernel<<<1, 32>>>();

    gru_persist<<<NCTA, NTHR, smem>>>(x, RT, bias, out, out_size);
}